// round 1
// baseline (speedup 1.0000x reference)
#include <cuda_runtime.h>

#define NWARPS 8
#define D 256            // feature dim
#define F4_PER_ROW (D/4) // 64 float4 per row

__device__ __forceinline__ float dot4(float4 a, float4 b) {
    return fmaf(a.x, b.x, fmaf(a.y, b.y, fmaf(a.z, b.z, a.w * b.w)));
}

__global__ __launch_bounds__(NWARPS * 32)
void ntxent_kernel(const float* __restrict__ zis,
                   const float* __restrict__ zjs,
                   const float* __restrict__ soft_labels,
                   float* __restrict__ out,
                   int nc)
{
    __shared__ float sl[12];
    __shared__ float wsum[NWARPS];

    const int tid  = threadIdx.x;
    const int warp = tid >> 5;
    const int lane = tid & 31;

    if (tid < 12) sl[tid] = soft_labels[tid];
    __syncthreads();

    const int g = blockIdx.x * NWARPS + warp;

    float acc = 0.0f;
    if (g < nc) {
        // Group g uses 4 rows:
        //   row0 = zjs[2g], row1 = zjs[2g+1], row2 = zis[2g], row3 = zis[2g+1]
        const float4* pj = reinterpret_cast<const float4*>(zjs) + (size_t)g * (2 * F4_PER_ROW);
        const float4* pi = reinterpret_cast<const float4*>(zis) + (size_t)g * (2 * F4_PER_ROW);

        // Front-batched loads: 8 independent LDG.128 per lane (MLP=8)
        float4 a0 = pj[lane];       float4 a1 = pj[lane + 32];   // row0
        float4 b0 = pj[lane + 64];  float4 b1 = pj[lane + 96];   // row1
        float4 c0 = pi[lane];       float4 c1 = pi[lane + 32];   // row2
        float4 d0 = pi[lane + 64];  float4 d1 = pi[lane + 96];   // row3

        // 10 partial sums per lane: 4 squared norms + 6 pairwise dots
        float v[10];
        v[0] = dot4(a0, a0) + dot4(a1, a1);   // |r0|^2
        v[1] = dot4(b0, b0) + dot4(b1, b1);   // |r1|^2
        v[2] = dot4(c0, c0) + dot4(c1, c1);   // |r2|^2
        v[3] = dot4(d0, d0) + dot4(d1, d1);   // |r3|^2
        v[4] = dot4(a0, b0) + dot4(a1, b1);   // s01
        v[5] = dot4(a0, c0) + dot4(a1, c1);   // s02
        v[6] = dot4(a0, d0) + dot4(a1, d1);   // s03
        v[7] = dot4(b0, c0) + dot4(b1, c1);   // s12
        v[8] = dot4(b0, d0) + dot4(b1, d1);   // s13
        v[9] = dot4(c0, d0) + dot4(c1, d1);   // s23

        // Warp butterfly reduction over all 10 values
        #pragma unroll
        for (int off = 16; off > 0; off >>= 1) {
            #pragma unroll
            for (int k = 0; k < 10; k++)
                v[k] += __shfl_xor_sync(0xFFFFFFFFu, v[k], off);
        }

        if (lane == 0) {
            const float EPS = 1e-8f;
            float r0 = 1.0f / fmaxf(sqrtf(v[0]), EPS);
            float r1 = 1.0f / fmaxf(sqrtf(v[1]), EPS);
            float r2 = 1.0f / fmaxf(sqrtf(v[2]), EPS);
            float r3 = 1.0f / fmaxf(sqrtf(v[3]), EPS);

            float s01 = v[4] * (r0 * r1);
            float s02 = v[5] * (r0 * r2);
            float s03 = v[6] * (r0 * r3);
            float s12 = v[7] * (r1 * r2);
            float s13 = v[8] * (r1 * r3);
            float s23 = v[9] * (r2 * r3);

            // logits per anchor i (before /T): (pos, neg0, neg1)
            // i=0: (s02, s01, s03)   i=1: (s13, s01, s12)
            // i=2: (s02, s12, s23)   i=3: (s13, s03, s23)
            float L[4][3] = {
                { s02, s01, s03 },
                { s13, s01, s12 },
                { s02, s12, s23 },
                { s13, s03, s23 }
            };
            const float invT = 2.0f;  // 1 / TEMPERATURE, T = 0.5

            #pragma unroll
            for (int i = 0; i < 4; i++) {
                float l0 = L[i][0] * invT;
                float l1 = L[i][1] * invT;
                float l2 = L[i][2] * invT;
                float m  = fmaxf(l0, fmaxf(l1, l2));
                float lse = m + logf(expf(l0 - m) + expf(l1 - m) + expf(l2 - m));
                // loss += -(logp_j) * w_j = (lse - l_j) * w_j
                acc += (lse - l0) * sl[i * 3 + 0]
                     + (lse - l1) * sl[i * 3 + 1]
                     + (lse - l2) * sl[i * 3 + 2];
            }
        }
    }

    if (lane == 0) wsum[warp] = acc;
    __syncthreads();

    if (tid == 0) {
        float t = 0.0f;
        #pragma unroll
        for (int w = 0; w < NWARPS; w++) t += wsum[w];
        // final scale: 1 / (2n) = 1 / (4 * nc)
        atomicAdd(out, t * (1.0f / (4.0f * (float)nc)));
    }
}

extern "C" void kernel_launch(void* const* d_in, const int* in_sizes, int n_in,
                              void* d_out, int out_size)
{
    const float* zis = (const float*)d_in[0];
    const float* zjs = (const float*)d_in[1];
    const float* sl  = (const float*)d_in[2];
    float* out = (float*)d_out;

    int n  = in_sizes[0] / D;  // 65536 rows
    int nc = n / 2;            // 32768 groups

    cudaMemsetAsync(out, 0, sizeof(float));
    int blocks = (nc + NWARPS - 1) / NWARPS;
    ntxent_kernel<<<blocks, NWARPS * 32>>>(zis, zjs, sl, out, nc);
}

// round 2
// speedup vs baseline: 1.1563x; 1.1563x over previous
#include <cuda_runtime.h>

#define NWARPS 8
#define D 256            // feature dim
#define F4_PER_ROW (D/4) // 64 float4 per row

__device__ __forceinline__ float dot4(float4 a, float4 b) {
    return fmaf(a.x, b.x, fmaf(a.y, b.y, fmaf(a.z, b.z, a.w * b.w)));
}

__global__ __launch_bounds__(NWARPS * 32)
void ntxent_kernel(const float* __restrict__ zis,
                   const float* __restrict__ zjs,
                   const float* __restrict__ soft_labels,
                   float* __restrict__ out,
                   int nc)
{
    __shared__ float sl[12];
    __shared__ float wsum[NWARPS];

    const int tid  = threadIdx.x;
    const int warp = tid >> 5;
    const int lane = tid & 31;

    if (tid < 12) sl[tid] = soft_labels[tid];
    __syncthreads();

    const int g = blockIdx.x * NWARPS + warp;

    float acc = 0.0f;
    if (g < nc) {
        // Group g uses 4 rows:
        //   row0 = zjs[2g], row1 = zjs[2g+1], row2 = zis[2g], row3 = zis[2g+1]
        const float4* pj = reinterpret_cast<const float4*>(zjs) + (size_t)g * (2 * F4_PER_ROW);
        const float4* pi = reinterpret_cast<const float4*>(zis) + (size_t)g * (2 * F4_PER_ROW);

        // Front-batched loads: 8 independent LDG.128 per lane (MLP=8)
        float4 a0 = pj[lane];       float4 a1 = pj[lane + 32];   // row0
        float4 b0 = pj[lane + 64];  float4 b1 = pj[lane + 96];   // row1
        float4 c0 = pi[lane];       float4 c1 = pi[lane + 32];   // row2
        float4 d0 = pi[lane + 64];  float4 d1 = pi[lane + 96];   // row3

        // 10 partial sums per lane: 4 squared norms + 6 pairwise dots
        float v[10];
        v[0] = dot4(a0, a0) + dot4(a1, a1);   // |r0|^2
        v[1] = dot4(b0, b0) + dot4(b1, b1);   // |r1|^2
        v[2] = dot4(c0, c0) + dot4(c1, c1);   // |r2|^2
        v[3] = dot4(d0, d0) + dot4(d1, d1);   // |r3|^2
        v[4] = dot4(a0, b0) + dot4(a1, b1);   // s01
        v[5] = dot4(a0, c0) + dot4(a1, c1);   // s02
        v[6] = dot4(a0, d0) + dot4(a1, d1);   // s03
        v[7] = dot4(b0, c0) + dot4(b1, c1);   // s12
        v[8] = dot4(b0, d0) + dot4(b1, d1);   // s13
        v[9] = dot4(c0, d0) + dot4(c1, d1);   // s23

        // Warp butterfly reduction over all 10 values (all lanes end with full sums)
        #pragma unroll
        for (int off = 16; off > 0; off >>= 1) {
            #pragma unroll
            for (int k = 0; k < 10; k++)
                v[k] += __shfl_xor_sync(0xFFFFFFFFu, v[k], off);
        }

        // Lanes 0..3 each handle one anchor's 3-way log-softmax (parallel MUFU)
        if (lane < 4) {
            // 1/max(||r||, 1e-8) == rsqrt(max(||r||^2, 1e-16))
            float r0 = rsqrtf(fmaxf(v[0], 1e-16f));
            float r1 = rsqrtf(fmaxf(v[1], 1e-16f));
            float r2 = rsqrtf(fmaxf(v[2], 1e-16f));
            float r3 = rsqrtf(fmaxf(v[3], 1e-16f));

            float s01 = v[4] * (r0 * r1);
            float s02 = v[5] * (r0 * r2);
            float s03 = v[6] * (r0 * r3);
            float s12 = v[7] * (r1 * r2);
            float s13 = v[8] * (r1 * r3);
            float s23 = v[9] * (r2 * r3);

            // logits per anchor i (before /T): (pos, neg0, neg1)
            // i=0: (s02, s01, s03)   i=1: (s13, s01, s12)
            // i=2: (s02, s12, s23)   i=3: (s13, s03, s23)
            float p  = (lane & 1)  ? s13 : s02;
            float n0 = (lane < 2)  ? s01 : ((lane == 2) ? s12 : s03);
            float n1 = (lane == 0) ? s03 : ((lane == 1) ? s12 : s23);

            const float invT = 2.0f;  // 1 / TEMPERATURE, T = 0.5
            float l0 = p  * invT;
            float l1 = n0 * invT;
            float l2 = n1 * invT;

            float m   = fmaxf(l0, fmaxf(l1, l2));
            float e   = __expf(l0 - m) + __expf(l1 - m) + __expf(l2 - m);
            float lse = m + __logf(e);

            acc = (lse - l0) * sl[lane * 3 + 0]
                + (lse - l1) * sl[lane * 3 + 1]
                + (lse - l2) * sl[lane * 3 + 2];
        }

        // Sum lanes 0..3 into lane 0 (lanes >=4 contribute 0)
        acc += __shfl_xor_sync(0xFFFFFFFFu, acc, 1);
        acc += __shfl_xor_sync(0xFFFFFFFFu, acc, 2);
    }

    if (lane == 0) wsum[warp] = acc;
    __syncthreads();

    if (tid == 0) {
        float t = 0.0f;
        #pragma unroll
        for (int w = 0; w < NWARPS; w++) t += wsum[w];
        // final scale: 1 / (2n) = 1 / (4 * nc)
        atomicAdd(out, t * (1.0f / (4.0f * (float)nc)));
    }
}

extern "C" void kernel_launch(void* const* d_in, const int* in_sizes, int n_in,
                              void* d_out, int out_size)
{
    const float* zis = (const float*)d_in[0];
    const float* zjs = (const float*)d_in[1];
    const float* sl  = (const float*)d_in[2];
    float* out = (float*)d_out;

    int n  = in_sizes[0] / D;  // 65536 rows
    int nc = n / 2;            // 32768 groups

    cudaMemsetAsync(out, 0, sizeof(float));
    int blocks = (nc + NWARPS - 1) / NWARPS;
    ntxent_kernel<<<blocks, NWARPS * 32>>>(zis, zjs, sl, out, nc);
}

// round 4
// speedup vs baseline: 1.1914x; 1.0303x over previous
#include <cuda_runtime.h>

#define NWARPS 8
#define D 256            // feature dim
#define F4_PER_ROW (D/4) // 64 float4 per row

__device__ __forceinline__ float dot4(float4 a, float4 b) {
    return fmaf(a.x, b.x, fmaf(a.y, b.y, fmaf(a.z, b.z, a.w * b.w)));
}

__global__ __launch_bounds__(NWARPS * 32, 4)
void ntxent_kernel(const float* __restrict__ zis,
                   const float* __restrict__ zjs,
                   const float* __restrict__ soft_labels,
                   float* __restrict__ out,
                   int nc)
{
    __shared__ float wsum[NWARPS];

    const int tid  = threadIdx.x;
    const int warp = tid >> 5;
    const int lane = tid & 31;

    const int g = blockIdx.x * NWARPS + warp;

    float acc = 0.0f;
    if (g < nc) {
        // Group g uses 4 rows:
        //   row0 = zjs[2g], row1 = zjs[2g+1], row2 = zis[2g], row3 = zis[2g+1]
        const float4* pj = reinterpret_cast<const float4*>(zjs) + (size_t)g * (2 * F4_PER_ROW);
        const float4* pi = reinterpret_cast<const float4*>(zis) + (size_t)g * (2 * F4_PER_ROW);

        // Front-batched loads: 8 independent LDG.128 per lane (MLP_p1 = 8).
        // launch_bounds(256,4) gives a ~64-reg budget so all 8 stay in flight.
        float4 a0 = pj[lane];       float4 a1 = pj[lane + 32];   // row0
        float4 b0 = pj[lane + 64];  float4 b1 = pj[lane + 96];   // row1
        float4 c0 = pi[lane];       float4 c1 = pi[lane + 32];   // row2
        float4 d0 = pi[lane + 64];  float4 d1 = pi[lane + 96];   // row3

        // 10 partial sums per lane: 4 squared norms + 6 pairwise dots
        float v[10];
        v[0] = dot4(a0, a0) + dot4(a1, a1);   // |r0|^2
        v[1] = dot4(b0, b0) + dot4(b1, b1);   // |r1|^2
        v[2] = dot4(c0, c0) + dot4(c1, c1);   // |r2|^2
        v[3] = dot4(d0, d0) + dot4(d1, d1);   // |r3|^2
        v[4] = dot4(a0, b0) + dot4(a1, b1);   // s01
        v[5] = dot4(a0, c0) + dot4(a1, c1);   // s02
        v[6] = dot4(a0, d0) + dot4(a1, d1);   // s03
        v[7] = dot4(b0, c0) + dot4(b1, c1);   // s12
        v[8] = dot4(b0, d0) + dot4(b1, d1);   // s13
        v[9] = dot4(c0, d0) + dot4(c1, d1);   // s23

        // Warp butterfly reduction over 10 values (10 independent dep-chains;
        // SHFL latency overlaps across values)
        #pragma unroll
        for (int off = 16; off > 0; off >>= 1) {
            #pragma unroll
            for (int k = 0; k < 10; k++)
                v[k] += __shfl_xor_sync(0xFFFFFFFFu, v[k], off);
        }

        // Lanes 0..3 each handle one anchor's 3-way log-softmax (parallel MUFU)
        if (lane < 4) {
            // 1/max(||r||, 1e-8) == rsqrt(max(||r||^2, 1e-16))
            float r0 = rsqrtf(fmaxf(v[0], 1e-16f));
            float r1 = rsqrtf(fmaxf(v[1], 1e-16f));
            float r2 = rsqrtf(fmaxf(v[2], 1e-16f));
            float r3 = rsqrtf(fmaxf(v[3], 1e-16f));

            float s01 = v[4] * (r0 * r1);
            float s02 = v[5] * (r0 * r2);
            float s03 = v[6] * (r0 * r3);
            float s12 = v[7] * (r1 * r2);
            float s13 = v[8] * (r1 * r3);
            float s23 = v[9] * (r2 * r3);

            // logits per anchor i (before /T): (pos, neg0, neg1)
            // i=0: (s02, s01, s03)   i=1: (s13, s01, s12)
            // i=2: (s02, s12, s23)   i=3: (s13, s03, s23)
            float p  = (lane & 1)  ? s13 : s02;
            float n0 = (lane < 2)  ? s01 : ((lane == 2) ? s12 : s03);
            float n1 = (lane == 0) ? s03 : ((lane == 1) ? s12 : s23);

            const float invT = 2.0f;  // 1 / TEMPERATURE, T = 0.5
            float l0 = p  * invT;
            float l1 = n0 * invT;
            float l2 = n1 * invT;

            float m   = fmaxf(l0, fmaxf(l1, l2));
            float e   = __expf(l0 - m) + __expf(l1 - m) + __expf(l2 - m);
            float lse = m + __logf(e);

            float w0 = __ldg(soft_labels + lane * 3 + 0);
            float w1 = __ldg(soft_labels + lane * 3 + 1);
            float w2 = __ldg(soft_labels + lane * 3 + 2);

            acc = (lse - l0) * w0 + (lse - l1) * w1 + (lse - l2) * w2;
        }

        // Sum lanes 0..3 into lane 0 (lanes >=4 contribute 0)
        acc += __shfl_xor_sync(0xFFFFFFFFu, acc, 1);
        acc += __shfl_xor_sync(0xFFFFFFFFu, acc, 2);
    }

    if (lane == 0) wsum[warp] = acc;
    __syncthreads();

    if (tid == 0) {
        float t = 0.0f;
        #pragma unroll
        for (int w = 0; w < NWARPS; w++) t += wsum[w];
        // final scale: 1 / (2n) = 1 / (4 * nc)
        atomicAdd(out, t * (1.0f / (4.0f * (float)nc)));
    }
}

extern "C" void kernel_launch(void* const* d_in, const int* in_sizes, int n_in,
                              void* d_out, int out_size)
{
    const float* zis = (const float*)d_in[0];
    const float* zjs = (const float*)d_in[1];
    const float* sl  = (const float*)d_in[2];
    float* out = (float*)d_out;

    int n  = in_sizes[0] / D;  // 65536 rows
    int nc = n / 2;            // 32768 groups

    cudaMemsetAsync(out, 0, sizeof(float));
    int blocks = (nc + NWARPS - 1) / NWARPS;
    ntxent_kernel<<<blocks, NWARPS * 32>>>(zis, zjs, sl, out, nc);
}